// round 9
// baseline (speedup 1.0000x reference)
#include <cuda_runtime.h>
#include <stdint.h>
#include <math.h>

#define HH 288
#define WW 288
#define HW (HH*WW)          // 82944
#define NIMG 4              // query b0,b1, key b0,b1
#define HQ 96
#define NPATCH (HQ*HQ)      // 9216
#define DPATCH 144

// ------------------- static device scratch (no allocations allowed) -------------------
__device__ float g_norm[(size_t)NIMG*6*HW];
__device__ float g_f64a[(size_t)NIMG*64*HW];
__device__ float g_f64b[(size_t)NIMG*64*HW];
__device__ float g_f128[(size_t)NIMG*128*HW];
__device__ float g_f16 [(size_t)NIMG*16*HW];
__device__ float g_patch[(size_t)NIMG*NPATCH*DPATCH]; // [img][patch][144]
// K in tf32 hi/lo, mma-fragment order: [b][kt(144)][kc(18)][j(8)][lane(32)][4]
// float4 per (..,lane) = {b0hi, b1hi, b0lo, b1lo}
#define KTSZ (64*DPATCH*2)  // 18432 floats per 64-key tile
__device__ float g_kfrag[(size_t)2*144*KTSZ];         // 21.2 MB

__constant__ float c_mean[6] = {0.485f, 0.456f, 0.406f, 0.5f, 0.5f, 0.5f};
__constant__ float c_istd[6] = {1.0f/0.229f, 1.0f/0.224f, 1.0f/0.225f,
                                1.0f/0.1f,   1.0f/0.1f,   1.0f/0.1f};

// ---- cp.async helpers ----
__device__ __forceinline__ void cp_async4(unsigned int dst, const void* src, int src_sz) {
    asm volatile("cp.async.ca.shared.global [%0], [%1], 4, %2;"
                 :: "r"(dst), "l"(src), "r"(src_sz));
}
__device__ __forceinline__ void cp_async16(unsigned int dst, const void* src) {
    asm volatile("cp.async.cg.shared.global [%0], [%1], 16;"
                 :: "r"(dst), "l"(src));
}
__device__ __forceinline__ void cp_commit() {
    asm volatile("cp.async.commit_group;");
}
__device__ __forceinline__ void cp_wait1() {
    asm volatile("cp.async.wait_group 1;");
}
__device__ __forceinline__ void cp_wait2() {
    asm volatile("cp.async.wait_group 2;");
}

// ---- tf32 helpers ----
__device__ __forceinline__ unsigned f2tf32(float x) {
    unsigned r;
    asm("cvt.rna.tf32.f32 %0, %1;" : "=r"(r) : "f"(x));
    return r;
}
__device__ __forceinline__ void mma_tf32(float* d, const unsigned* a,
                                         unsigned b0, unsigned b1) {
    asm volatile(
        "mma.sync.aligned.m16n8k8.row.col.f32.tf32.tf32.f32 "
        "{%0,%1,%2,%3}, {%4,%5,%6,%7}, {%8,%9}, {%0,%1,%2,%3};\n"
        : "+f"(d[0]), "+f"(d[1]), "+f"(d[2]), "+f"(d[3])
        : "r"(a[0]), "r"(a[1]), "r"(a[2]), "r"(a[3]), "r"(b0), "r"(b1));
}

// ------------------- (x - mean)/std into g_norm -------------------
__global__ void k_norm(const float* __restrict__ q, const float* __restrict__ k) {
    int i = blockIdx.x * 256 + threadIdx.x;
    if (i >= NIMG*6*HW) return;
    int img = i / (6*HW);
    int rem = i - img * (6*HW);
    int c = rem / HW;
    float v = (img < 2) ? q[(size_t)img*6*HW + rem] : k[(size_t)(img-2)*6*HW + rem];
    g_norm[i] = (v - c_mean[c]) * c_istd[c];
}

// ------------------- 3x3 conv, pad=1, ReLU (unchanged from R7) -------------------
#define CTILE (34*34)
template<int CIN, int COUT>
__global__ __launch_bounds__(256, 2)
void k_conv3x3(const float* __restrict__ in, const float* __restrict__ w,
               const float* __restrict__ bias, float* __restrict__ out) {
    __shared__ float tile[4][2*CTILE];
    __shared__ float w_all[CIN*144];

    const int tx = threadIdx.x, ty = threadIdx.y;
    const int tid = ty * 32 + tx;
    const int groups = COUT / 16;
    const int img = blockIdx.z / groups;
    const int cg  = blockIdx.z % groups;
    const int bx = blockIdx.x * 32, by = blockIdx.y * 32;
    const int S = CIN / 2;

    unsigned int tile_base = (unsigned int)__cvta_generic_to_shared(&tile[0][0]);
    unsigned int w_base    = (unsigned int)__cvta_generic_to_shared(&w_all[0]);

    const bool has5 = (tid < CTILE - 4*256);   // 132
    int  g_off[5];
    int  sz  [5];
    unsigned int s_off[5];
#pragma unroll
    for (int t = 0; t < 5; ++t) {
        int i = tid + t*256;
        if (i >= CTILE) i = 0;
        int r = i / 34, c = i - r*34;
        int gy = by - 1 + r, gx = bx - 1 + c;
        bool ok = (gy >= 0) & (gy < HH) & (gx >= 0) & (gx < WW);
        int cy = min(max(gy, 0), HH-1), cx = min(max(gx, 0), WW-1);
        g_off[t] = cy*WW + cx;
        sz  [t] = ok ? 4 : 0;
        s_off[t] = (unsigned)i * 4u;
    }

    float acc[16][4];
#pragma unroll
    for (int oc = 0; oc < 16; ++oc)
#pragma unroll
        for (int p = 0; p < 4; ++p) acc[oc][p] = 0.0f;

    auto issue_stage = [&](int st) {
        int buf = st & 3;
        const float* inp0 = in + ((size_t)(img*CIN + st*2)) * HW;
#pragma unroll
        for (int ch = 0; ch < 2; ++ch) {
            const float* inp = inp0 + (size_t)ch * HW;
            unsigned int tb = tile_base + (buf*2 + ch) * (CTILE*4);
#pragma unroll
            for (int t = 0; t < 4; ++t)
                cp_async4(tb + s_off[t], inp + g_off[t], sz[t]);
            if (has5)
                cp_async4(tb + s_off[4], inp + g_off[4], sz[4]);
        }
    };

    for (int idx = tid; idx < CIN*144; idx += 256) {
        int cin = idx / 144, r = idx % 144;
        int kk = r >> 4, oc = r & 15;
        cp_async4(w_base + idx*4, w + ((size_t)(cg*16 + oc) * CIN + cin) * 9 + kk, 4);
    }
    issue_stage(0);
    cp_commit();
    if (S > 1) issue_stage(1);
    cp_commit();
    if (S > 2) issue_stage(2);
    cp_commit();

    for (int s = 0; s < S; ++s) {
        cp_wait2();
        __syncthreads();
        if (s + 3 < S) issue_stage(s + 3);
        cp_commit();

        const int buf = s & 3;
#pragma unroll
        for (int ch = 0; ch < 2; ++ch) {
            const float*  T  = &tile[buf][ch*CTILE];
            const float4* W4 = (const float4*)&w_all[(s*2 + ch)*144];
#pragma unroll
            for (int kh = 0; kh < 3; ++kh) {
#pragma unroll
                for (int kw = 0; kw < 3; ++kw) {
                    const int kk = kh*3 + kw;
                    float v0 = T[(ty      + kh)*34 + tx + kw];
                    float v1 = T[(ty +  8 + kh)*34 + tx + kw];
                    float v2 = T[(ty + 16 + kh)*34 + tx + kw];
                    float v3 = T[(ty + 24 + kh)*34 + tx + kw];
#pragma unroll
                    for (int q = 0; q < 4; ++q) {
                        float4 wq = W4[kk*4 + q];
                        acc[q*4+0][0] += v0*wq.x; acc[q*4+0][1] += v1*wq.x;
                        acc[q*4+0][2] += v2*wq.x; acc[q*4+0][3] += v3*wq.x;
                        acc[q*4+1][0] += v0*wq.y; acc[q*4+1][1] += v1*wq.y;
                        acc[q*4+1][2] += v2*wq.y; acc[q*4+1][3] += v3*wq.y;
                        acc[q*4+2][0] += v0*wq.z; acc[q*4+2][1] += v1*wq.z;
                        acc[q*4+2][2] += v2*wq.z; acc[q*4+2][3] += v3*wq.z;
                        acc[q*4+3][0] += v0*wq.w; acc[q*4+3][1] += v1*wq.w;
                        acc[q*4+3][2] += v2*wq.w; acc[q*4+3][3] += v3*wq.w;
                    }
                }
            }
        }
    }

#pragma unroll
    for (int oc = 0; oc < 16; ++oc) {
        int ocg = cg*16 + oc;
        float bv = bias[ocg];
#pragma unroll
        for (int p = 0; p < 4; ++p) {
            int y = by + ty + p*8;
            float v = acc[oc][p] + bv;
            v = fmaxf(v, 0.0f);
            out[((size_t)(img*COUT + ocg)) * HW + y*WW + bx + tx] = v;
        }
    }
}

// ------------------- 1x1 conv 128->16 + leaky_relu(0.2) -------------------
__global__ void k_conv4(const float* __restrict__ w4, const float* __restrict__ b4) {
    __shared__ float ws[16*128];
    __shared__ float bs[16];
    int tid = threadIdx.x;
    for (int i = tid; i < 16*128; i += 256) ws[i] = w4[i];
    if (tid < 16) bs[tid] = b4[tid];
    __syncthreads();

    int pix = blockIdx.x * 256 + tid;
    int img = blockIdx.y;
    float acc[16];
#pragma unroll
    for (int c = 0; c < 16; ++c) acc[c] = bs[c];

    const float* in = g_f128 + (size_t)img*128*HW + pix;
    for (int ci = 0; ci < 128; ++ci) {
        float v = in[(size_t)ci * HW];
#pragma unroll
        for (int c = 0; c < 16; ++c) acc[c] += ws[c*128 + ci] * v;
    }
    float* out = g_f16 + (size_t)img*16*HW + pix;
#pragma unroll
    for (int c = 0; c < 16; ++c) {
        float v = acc[c];
        out[(size_t)c*HW] = (v > 0.0f) ? v : 0.2f * v;
    }
}

// ------------------- unfold k3s3 + per-patch L2 normalize -------------------
__global__ void k_patch() {
    int gw = (blockIdx.x * blockDim.x + threadIdx.x) >> 5;
    int lane = threadIdx.x & 31;
    if (gw >= NIMG * NPATCH) return;
    int img = gw / NPATCH;
    int p   = gw % NPATCH;
    int hq = p / HQ, wq = p % HQ;
    const float* f = g_f16 + (size_t)img*16*HW;

    float v[5];
    float ss = 0.0f;
#pragma unroll
    for (int t = 0; t < 5; ++t) {
        int d = lane + t*32;
        float x = 0.0f;
        if (d < DPATCH) {
            int c = d / 9, kk = d % 9;
            int y = hq*3 + kk/3, xx = wq*3 + kk%3;
            x = f[(size_t)c*HW + y*WW + xx];
        }
        v[t] = x;
        ss += x * x;
    }
#pragma unroll
    for (int m = 16; m; m >>= 1) ss += __shfl_xor_sync(0xffffffffu, ss, m);
    float inv = 1.0f / fmaxf(sqrtf(ss), 1e-12f);
    float* o = g_patch + ((size_t)img*NPATCH + p) * DPATCH;
#pragma unroll
    for (int t = 0; t < 5; ++t) {
        int d = lane + t*32;
        if (d < DPATCH) o[d] = v[t] * inv;
    }
}

// ------------------- split key patches into tf32 hi/lo, mma-fragment order ----------
// one thread per (b, kt, kc, j, lane) -> float4 {b0hi, b1hi, b0lo, b1lo}
__global__ void k_split() {
    int idx = blockIdx.x * 256 + threadIdx.x;
    if (idx >= 2*144*18*8*32) return;
    int lane = idx & 31;
    int j    = (idx >> 5) & 7;
    int t    = idx >> 8;             // b*144*18 + kt*18 + kc
    int kc   = t % 18;
    int kt   = (t / 18) % 144;
    int b    = t / (18*144);

    int n  = kt*64 + j*8 + (lane >> 2);
    int k0 = kc*8 + (lane & 3);
    const float* src = g_patch + ((size_t)(2 + b)*NPATCH + n) * DPATCH;
    float v0 = src[k0];
    float v1 = src[k0 + 4];
    unsigned h0 = f2tf32(v0);
    unsigned h1 = f2tf32(v1);
    unsigned l0 = f2tf32(v0 - __uint_as_float(h0));
    unsigned l1 = f2tf32(v1 - __uint_as_float(h1));
    ((float4*)g_kfrag)[idx] = make_float4(__uint_as_float(h0), __uint_as_float(h1),
                                          __uint_as_float(l0), __uint_as_float(l1));
}

// ------------------- correlation: 3xTF32 tensor-core GEMM fused max/argmax ----------
// grid: (72 m-tiles, 2 batches)  block: 256 = 8 warps; each warp: 16 q rows x 64 keys
// smem: Q raw fp32 [128 x 148] + double-buffered K frag tiles [2][18432]
#define QSTRIDE 148
#define KTILES 144
__global__ __launch_bounds__(256, 1)
void k_corr(float* __restrict__ out, int out_size) {
    extern __shared__ float smf[];
    float* q_s = smf;                      // 128*148 floats
    float* k_s = smf + 128*QSTRIDE;        // 2 * KTSZ floats

    const int tid  = threadIdx.x;
    const int warp = tid >> 5;
    const int lane = tid & 31;
    const int b  = blockIdx.y;
    const int mt = blockIdx.x;

    unsigned int q_base = (unsigned int)__cvta_generic_to_shared(q_s);
    unsigned int k_base = (unsigned int)__cvta_generic_to_shared(k_s);

    const float4* qg  = (const float4*)(g_patch + (size_t)b * NPATCH * DPATCH);
    const float4* kfg = (const float4*)(g_kfrag + (size_t)b * KTILES * KTSZ);

    auto issue_k = [&](int bb, int kt) {
        unsigned int base = k_base + bb * (KTSZ*4);
        const float4* src = kfg + (size_t)kt * (KTSZ/4);
        for (int i = tid; i < KTSZ/4; i += 256)
            cp_async16(base + i*16, src + i);
    };

    // Q: rows mt*128..+127, padded stride 148
    for (int i = tid; i < 128*36; i += 256) {
        int r = i / 36, c = i % 36;
        cp_async16(q_base + (r*QSTRIDE + c*4)*4, qg + (size_t)(mt*128 + r)*36 + c);
    }
    issue_k(0, 0);
    cp_commit();
    issue_k(1, 1);
    cp_commit();

    const int qr   = warp*16 + (lane >> 2);   // A row (and +8)
    const int kcol = lane & 3;

    float rmax[2];
    int   ridx[2];
    rmax[0] = rmax[1] = -1e30f;
    ridx[0] = ridx[1] = 0x7fffffff;

    for (int kt = 0; kt < KTILES; ++kt) {
        cp_wait1();
        __syncthreads();

        const float4* kb = (const float4*)(k_s + (kt & 1) * KTSZ);

        float d[8][4];
#pragma unroll
        for (int j = 0; j < 8; ++j)
#pragma unroll
            for (int v = 0; v < 4; ++v) d[j][v] = 0.0f;

#pragma unroll 2
        for (int kc = 0; kc < 18; ++kc) {
            float a0 = q_s[ qr      *QSTRIDE + kc*8 + kcol    ];
            float a1 = q_s[(qr + 8) *QSTRIDE + kc*8 + kcol    ];
            float a2 = q_s[ qr      *QSTRIDE + kc*8 + kcol + 4];
            float a3 = q_s[(qr + 8) *QSTRIDE + kc*8 + kcol + 4];
            unsigned ahi[4], alo[4];
            ahi[0] = f2tf32(a0); alo[0] = f2tf32(a0 - __uint_as_float(ahi[0]));
            ahi[1] = f2tf32(a1); alo[1] = f2tf32(a1 - __uint_as_float(ahi[1]));
            ahi[2] = f2tf32(a2); alo[2] = f2tf32(a2 - __uint_as_float(ahi[2]));
            ahi[3] = f2tf32(a3); alo[3] = f2tf32(a3 - __uint_as_float(ahi[3]));
#pragma unroll
            for (int j = 0; j < 8; ++j) {
                float4 bf = kb[(kc*8 + j)*32 + lane];   // {b0hi,b1hi,b0lo,b1lo}
                unsigned bh0 = __float_as_uint(bf.x), bh1 = __float_as_uint(bf.y);
                unsigned bl0 = __float_as_uint(bf.z), bl1 = __float_as_uint(bf.w);
                mma_tf32(d[j], ahi, bh0, bh1);
                mma_tf32(d[j], ahi, bl0, bl1);
                mma_tf32(d[j], alo, bh0, bh1);
            }
        }

        // running max/argmax; ascending index order + strict > = first-max semantics
#pragma unroll
        for (int j = 0; j < 8; ++j) {
            int i0 = kt*64 + j*8 + 2*kcol;
            if (d[j][0] > rmax[0]) { rmax[0] = d[j][0]; ridx[0] = i0; }
            if (d[j][1] > rmax[0]) { rmax[0] = d[j][1]; ridx[0] = i0 + 1; }
            if (d[j][2] > rmax[1]) { rmax[1] = d[j][2]; ridx[1] = i0; }
            if (d[j][3] > rmax[1]) { rmax[1] = d[j][3]; ridx[1] = i0 + 1; }
        }

        __syncthreads();
        if (kt + 2 < KTILES) issue_k(kt & 1, kt + 2);
        cp_commit();
    }

    // reduce across the 4 lanes sharing each row (xor 1, 2 within lane%4 group)
#pragma unroll
    for (int p = 0; p < 2; ++p) {
        float bv = rmax[p];
        int   bi = ridx[p];
#pragma unroll
        for (int m = 1; m <= 2; m <<= 1) {
            float ov = __shfl_xor_sync(0xffffffffu, bv, m);
            int   oi = __shfl_xor_sync(0xffffffffu, bi, m);
            if (ov > bv || (ov == bv && oi < bi)) { bv = ov; bi = oi; }
        }
        if (kcol == 0) {
            int m = mt*128 + warp*16 + (lane >> 2) + p*8;
            out[b*NPATCH + m] = bv;
            if (out_size >= 4*NPATCH)
                out[2*NPATCH + b*NPATCH + m] = (float)bi;
        }
    }
}

// ------------------- launch -------------------
extern "C" void kernel_launch(void* const* d_in, const int* in_sizes, int n_in,
                              void* d_out, int out_size) {
    const float* query = (const float*)d_in[0];
    const float* key   = (const float*)d_in[1];
    const float* w1 = (const float*)d_in[3];  const float* b1 = (const float*)d_in[4];
    const float* w2 = (const float*)d_in[5];  const float* b2 = (const float*)d_in[6];
    const float* w3 = (const float*)d_in[7];  const float* b3 = (const float*)d_in[8];
    const float* w4 = (const float*)d_in[9];  const float* b4 = (const float*)d_in[10];
    float* out = (float*)d_out;

    float *p_norm, *p_a, *p_b, *p_128;
    cudaGetSymbolAddress((void**)&p_norm, g_norm);
    cudaGetSymbolAddress((void**)&p_a,    g_f64a);
    cudaGetSymbolAddress((void**)&p_b,    g_f64b);
    cudaGetSymbolAddress((void**)&p_128,  g_f128);

    const int corr_smem = (128*QSTRIDE + 2*KTSZ) * (int)sizeof(float);  // 223232 B
    cudaFuncSetAttribute(k_corr, cudaFuncAttributeMaxDynamicSharedMemorySize, corr_smem);

    k_norm<<<(NIMG*6*HW + 255)/256, 256>>>(query, key);

    dim3 blk(32, 8);
    k_conv3x3<6, 64 ><<<dim3(9, 9, NIMG*4),  blk>>>(p_norm, w1, b1, p_a);
    k_conv3x3<64, 64><<<dim3(9, 9, NIMG*4),  blk>>>(p_a,    w2, b2, p_b);
    k_conv3x3<64,128><<<dim3(9, 9, NIMG*8),  blk>>>(p_b,    w3, b3, p_128);

    k_conv4<<<dim3(HW/256, NIMG), 256>>>(w4, b4);

    k_patch<<<(NIMG*NPATCH*32 + 255)/256, 256>>>();

    k_split<<<(2*144*18*8*32 + 255)/256, 256>>>();

    k_corr<<<dim3(NPATCH/128, 2), 256, corr_smem>>>(out, out_size);
}